// round 15
// baseline (speedup 1.0000x reference)
#include <cuda_runtime.h>
#include <cuda_fp16.h>
#include <math.h>

#define BTOT 262144
#define NBT  2048   // 128-row blocks (gemm1 + tail)

__device__ unsigned g_hh[(size_t)BTOT * 128];   // h fp16 pairs
__device__ float    g_psum[256 * NBT];
__device__ float    g_psq [256 * NBT];
__device__ float    g_A[256], g_Bb[256], g_b2p[128];
__device__ unsigned g_w1p[256 * 64];            // W1 fp16 pairs [n][pw]
__device__ unsigned short g_w2f[128 * 256];     // W2' fp16 [n][k]
__device__ unsigned g_we1p[5 * 128 * 64];       // We1 fp16 pairs
__device__ unsigned g_w2c [5 * 16 * 68];        // We2 fp16 pairs [g][a][j-pw]

__device__ __forceinline__ void mma16h(float* c, const unsigned* a, const unsigned* b) {
    asm volatile("mma.sync.aligned.m16n8k16.row.col.f32.f16.f16.f32 "
        "{%0,%1,%2,%3},{%4,%5,%6,%7},{%8,%9},{%0,%1,%2,%3};"
        : "+f"(c[0]), "+f"(c[1]), "+f"(c[2]), "+f"(c[3])
        : "r"(a[0]), "r"(a[1]), "r"(a[2]), "r"(a[3]), "r"(b[0]), "r"(b[1]));
}
__device__ __forceinline__ unsigned packh(float a, float b) {
    __half2 h = __floats2half2_rn(a, b); return *(unsigned*)&h;
}
__device__ __forceinline__ void packpairh(float v0, float v1, unsigned& hp, unsigned& lp) {
    __half h0 = __float2half_rn(v0), h1 = __float2half_rn(v1);
    hp = (unsigned)*(unsigned short*)&h0 | ((unsigned)*(unsigned short*)&h1 << 16);
    lp = packh(v0 - __half2float(h0), v1 - __half2float(h1));
}
__device__ __forceinline__ void cpa16(void* dst, const void* src) {
    unsigned d = (unsigned)__cvta_generic_to_shared(dst);
    asm volatile("cp.async.cg.shared.global [%0],[%1],16;\n" :: "r"(d), "l"(src));
}
#define CPCOMMIT asm volatile("cp.async.commit_group;\n")
#define CPWAIT0  asm volatile("cp.async.wait_group 0;\n")
#define CPWAIT1  asm volatile("cp.async.wait_group 1;\n")

// ------------------- prep -------------------
__global__ void k_prep(const float* __restrict__ W1, const float* __restrict__ We1,
                       const float* __restrict__ We2) {
    int idx = blockIdx.x * blockDim.x + threadIdx.x, st = gridDim.x * blockDim.x;
    for (int i = idx; i < 256 * 64; i += st) {
        int n = i >> 6, pw = i & 63;
        int k0 = 2 * pw, k1 = 2 * pw + 1;
        float v0 = (k0 < 100) ? W1[k0 * 256 + n] : 0.f;
        float v1 = (k1 < 100) ? W1[k1 * 256 + n] : 0.f;
        g_w1p[i] = packh(v0, v1);
    }
    for (int i = idx; i < 5 * 128 * 64; i += st) {
        int g = i >> 13, r = i & 8191, j = r >> 6, ep = r & 63;
        int sub = j >> 6, jl = j & 63;
        float v0 = We1[((size_t)(2 * g + sub) * 128 + 2 * ep) * 64 + jl];
        float v1 = We1[((size_t)(2 * g + sub) * 128 + 2 * ep + 1) * 64 + jl];
        g_we1p[i] = packh(v0, v1);
    }
    for (int i = idx; i < 5 * 16 * 68; i += st) {
        int g = i / 1088, r = i - g * 1088, a = r / 68, pw = r - a * 68;
        float v0 = 0.f, v1 = 0.f;
        if (a < 10 && pw < 64) {
            int j0 = 2 * pw, j1 = 2 * pw + 1;
            v0 = We2[(size_t)((2 * g + (j0 >> 6)) * 64 + (j0 & 63)) * 10 + a];
            v1 = We2[(size_t)((2 * g + (j1 >> 6)) * 64 + (j1 & 63)) * 10 + a];
        }
        g_w2c[i] = packh(v0, v1);
    }
}

// -- K1: h = relu(state@W1+b1). 128x256 tile, 512 thr, single fp16, K=112. --
__global__ __launch_bounds__(512, 2)
void k_gemm1(const float* __restrict__ state, const float* __restrict__ b1) {
    extern __shared__ unsigned sm[];
    unsigned* As = sm;             // [128][36]
    unsigned* Bs = sm + 4608;      // [256][36]; end 13824 words
    const int t = threadIdx.x, w = t >> 5, lane = t & 31;
    const int gid = lane >> 2, q = lane & 3;
    const int wm = w >> 2, wn = w & 3, rowb = wm * 32, colb = wn * 64;
    const size_t row0 = (size_t)blockIdx.x * 128;

    float acc[2][8][4];
#pragma unroll
    for (int m = 0; m < 2; m++)
#pragma unroll
        for (int na = 0; na < 8; na++)
#pragma unroll
            for (int j = 0; j < 4; j++) acc[m][na][j] = 0.f;

    for (int kc = 0; kc < 2; kc++) {
        __syncthreads();
        {
            int r = t >> 2, sl = t & 3, c0 = kc * 64 + sl * 16;
            float vv[16];
#pragma unroll
            for (int u = 0; u < 4; u++) {
                int k = c0 + u * 4;
                float4 x = (k < 100) ? *(const float4*)(state + (row0 + r) * 100 + k)
                                     : make_float4(0.f, 0.f, 0.f, 0.f);
                vv[4 * u] = x.x; vv[4 * u + 1] = x.y; vv[4 * u + 2] = x.z; vv[4 * u + 3] = x.w;
            }
            unsigned H[8];
#pragma unroll
            for (int u = 0; u < 8; u++) H[u] = packh(vv[2 * u], vv[2 * u + 1]);
            *(uint4*)(As + r * 36 + sl * 8)     = make_uint4(H[0], H[1], H[2], H[3]);
            *(uint4*)(As + r * 36 + sl * 8 + 4) = make_uint4(H[4], H[5], H[6], H[7]);
        }
        for (int i = t; i < 2048; i += 512) {
            int n = i >> 3, c8 = i & 7;
            *(uint4*)(Bs + n * 36 + c8 * 4) =
                *(const uint4*)(g_w1p + (size_t)n * 64 + kc * 32 + c8 * 4);
        }
        __syncthreads();
        const int kcnt = kc ? 3 : 4;
        for (int ks = 0; ks < kcnt; ks++) {
            unsigned ah[2][4];
#pragma unroll
            for (int m = 0; m < 2; m++) {
                int b = (rowb + 16 * m + gid) * 36 + ks * 8 + q;
                ah[m][0] = As[b]; ah[m][1] = As[b + 288]; ah[m][2] = As[b + 4]; ah[m][3] = As[b + 292];
            }
#pragma unroll
            for (int na = 0; na < 8; na++) {
                int bb = (colb + 8 * na + gid) * 36 + ks * 8 + q;
                unsigned bh[2] = {Bs[bb], Bs[bb + 4]};
#pragma unroll
                for (int m = 0; m < 2; m++) mma16h(acc[m][na], ah[m], bh);
            }
        }
    }
    __syncthreads();
    float* sums = (float*)sm;      // [4][256]
    float* sqs  = sums + 1024;
#pragma unroll
    for (int na = 0; na < 8; na++) {
        int cg = colb + 8 * na + 2 * q;
        float bias0 = b1[cg], bias1 = b1[cg + 1];
        float p0 = 0.f, p1 = 0.f, q0 = 0.f, q1 = 0.f;
#pragma unroll
        for (int m = 0; m < 2; m++) {
            size_t r = row0 + rowb + 16 * m + gid;
            float v00 = fmaxf(acc[m][na][0] + bias0, 0.f), v01 = fmaxf(acc[m][na][1] + bias1, 0.f);
            float v10 = fmaxf(acc[m][na][2] + bias0, 0.f), v11 = fmaxf(acc[m][na][3] + bias1, 0.f);
            g_hh[r * 128 + (cg >> 1)]       = packh(v00, v01);
            g_hh[(r + 8) * 128 + (cg >> 1)] = packh(v10, v11);
            p0 += v00 + v10; p1 += v01 + v11;
            q0 += v00 * v00 + v10 * v10; q1 += v01 * v01 + v11 * v11;
        }
#pragma unroll
        for (int off = 4; off <= 16; off <<= 1) {
            p0 += __shfl_xor_sync(0xffffffffu, p0, off);
            p1 += __shfl_xor_sync(0xffffffffu, p1, off);
            q0 += __shfl_xor_sync(0xffffffffu, q0, off);
            q1 += __shfl_xor_sync(0xffffffffu, q1, off);
        }
        if (gid == 0) {
            sums[wm * 256 + cg] = p0; sums[wm * 256 + cg + 1] = p1;
            sqs [wm * 256 + cg] = q0; sqs [wm * 256 + cg + 1] = q1;
        }
    }
    __syncthreads();
    if (t < 256) {
        g_psum[t * NBT + blockIdx.x] = sums[t] + sums[256 + t] + sums[512 + t] + sums[768 + t];
        g_psq [t * NBT + blockIdx.x] = sqs[t] + sqs[256 + t] + sqs[512 + t] + sqs[768 + t];
    }
}

// ------------------- K2: BN stats finalize -------------------
__global__ __launch_bounds__(256)
void k_stats(const float* __restrict__ gamma, const float* __restrict__ beta) {
    const int c = blockIdx.x, t = threadIdx.x;
    float s = 0.f, qq = 0.f;
    for (int i = t; i < NBT; i += 256) { s += g_psum[c * NBT + i]; qq += g_psq[c * NBT + i]; }
#pragma unroll
    for (int off = 16; off; off >>= 1) {
        s += __shfl_xor_sync(0xffffffffu, s, off);
        qq += __shfl_xor_sync(0xffffffffu, qq, off);
    }
    __shared__ float ss[8], sq[8];
    if ((t & 31) == 0) { ss[t >> 5] = s; sq[t >> 5] = qq; }
    __syncthreads();
    if (t == 0) {
        float S = 0.f, Q = 0.f;
#pragma unroll
        for (int wv = 0; wv < 8; wv++) { S += ss[wv]; Q += sq[wv]; }
        const float inv_n = 1.f / (float)BTOT;
        float mu = S * inv_n;
        float var = Q * inv_n - mu * mu;
        float rstd = rsqrtf(var + 1e-5f);
        float gg = gamma[c];
        g_A[c] = rstd * gg;
        g_Bb[c] = beta[c] - mu * rstd * gg;
    }
}

// ------------- K2b: fold BN into W2 (fp16) + b2' ---------------
__global__ __launch_bounds__(256)
void k_fold(const float* __restrict__ W2, const float* __restrict__ b2) {
    const int n = blockIdx.x, k = threadIdx.x;
    float wv = W2[k * 128 + n];
    __half hf = __float2half_rn(g_A[k] * wv);
    g_w2f[n * 256 + k] = *(unsigned short*)&hf;
    float p = g_Bb[k] * wv;
#pragma unroll
    for (int off = 16; off; off >>= 1) p += __shfl_xor_sync(0xffffffffu, p, off);
    __shared__ float red[8];
    if ((k & 31) == 0) red[k >> 5] = p;
    __syncthreads();
    if (k == 0) {
        float S = 0.f;
#pragma unroll
        for (int i = 0; i < 8; i++) S += red[i];
        g_b2p[n] = b2[n] + S;
    }
}

// -- K3: fused tail (128 rows, 512 thr): enc GEMM + dist + softmax + experts
__global__ __launch_bounds__(512, 2)
void k_tail(const float* __restrict__ att, const float* __restrict__ be1,
            const float* __restrict__ be2, float* __restrict__ out) {
    extern __shared__ unsigned sm[];
    unsigned* Bs  = sm + 9216;           // phase A: A-dbuf 0/4608, Bs [128][36]
    unsigned* eH   = sm;                 // [128][68]
    unsigned* eL   = sm + 8704;          // [128][68] (dead after distance)
    unsigned* wbuf = sm + 8704;          // [128][68] We1 -> eh
    unsigned* atH = sm + 17408;          // [16][68]
    unsigned* atL = sm + 18496;
    float* b2ps = (float*)(sm + 19584);  // [128]
    float* asqS = (float*)(sm + 19712);  // [16]
    float* dotS = (float*)(sm + 19728);  // [128][20]
    float* esqP = (float*)(sm + 22288);  // [4][128]
    float* sS   = (float*)(sm + 22800);  // [128][12]
    float* sBe  = (float*)(sm + 24336);  // [128]
    float* be2S = (float*)(sm + 24464);  // [112]
    unsigned* B2 = sm + 24576;           // [16][68]; total 25664 words
    const int t = threadIdx.x, w = t >> 5, lane = t & 31;
    const int gid = lane >> 2, q = lane & 3;
    const int wm = w >> 2, wn = w & 3, rowb = wm * 32, colb = wn * 32;
    const size_t row0 = (size_t)blockIdx.x * 128;
    const unsigned* w2w = (const unsigned*)g_w2f;

    for (int i = t; i < 1088; i += 512) {
        int n = i / 68, pw = i - n * 68;
        float v0 = 0.f, v1 = 0.f;
        if (n < 10 && pw < 64) { v0 = att[n * 128 + 2 * pw]; v1 = att[n * 128 + 2 * pw + 1]; }
        unsigned hp, lp;
        packpairh(v0, v1, hp, lp);
        atH[i] = hp; atL[i] = lp;
    }
    if (t < 128) b2ps[t] = g_b2p[t];
    if (t >= 128 && t < 144) {
        int k = t - 128;
        float a2 = 0.f;
        if (k < 10)
            for (int c = 0; c < 128; c++) { float x = att[k * 128 + c]; a2 += x * x; }
        asqS[k] = a2;
    }
    if (t >= 144 && t < 244) be2S[t - 144] = be2[t - 144];

    float acc[2][4][4];
#pragma unroll
    for (int m = 0; m < 2; m++)
#pragma unroll
        for (int na = 0; na < 4; na++)
#pragma unroll
            for (int j = 0; j < 4; j++) acc[m][na][j] = 0.f;

    for (int i = t; i < 1024; i += 512) {
        int r = i >> 3, c8 = i & 7;
        cpa16(sm + r * 36 + c8 * 4, g_hh + (row0 + r) * 128 + c8 * 4);
    }
    CPCOMMIT;
    for (int kc = 0; kc < 4; kc++) {
        if (kc < 3) {
            unsigned* dst = sm + ((kc + 1) & 1) * 4608;
            for (int i = t; i < 1024; i += 512) {
                int r = i >> 3, c8 = i & 7;
                cpa16(dst + r * 36 + c8 * 4, g_hh + (row0 + r) * 128 + (kc + 1) * 32 + c8 * 4);
            }
            CPCOMMIT;
        }
        for (int i = t; i < 1024; i += 512) {
            int n = i >> 3, c8 = i & 7;
            *(uint4*)(Bs + n * 36 + c8 * 4) = *(const uint4*)(w2w + (size_t)n * 128 + kc * 32 + c8 * 4);
        }
        if (kc < 3) { CPWAIT1; } else { CPWAIT0; }
        __syncthreads();
        unsigned* As = sm + (kc & 1) * 4608;
#pragma unroll
        for (int ks = 0; ks < 4; ks++) {
            unsigned ah[2][4];
#pragma unroll
            for (int m = 0; m < 2; m++) {
                int b = (rowb + 16 * m + gid) * 36 + ks * 8 + q;
                ah[m][0] = As[b]; ah[m][1] = As[b + 288]; ah[m][2] = As[b + 4]; ah[m][3] = As[b + 292];
            }
#pragma unroll
            for (int na = 0; na < 4; na++) {
                int bb = (colb + 8 * na + gid) * 36 + ks * 8 + q;
                unsigned bh[2] = {Bs[bb], Bs[bb + 4]};
#pragma unroll
                for (int m = 0; m < 2; m++) mma16h(acc[m][na], ah[m], bh);
            }
        }
        __syncthreads();
    }
    float p2[4] = {0.f, 0.f, 0.f, 0.f};
#pragma unroll
    for (int na = 0; na < 4; na++) {
        int cl = colb + 8 * na + 2 * q, pw = (cl >> 1);
        float bb0 = b2ps[cl], bb1 = b2ps[cl + 1];
#pragma unroll
        for (int m = 0; m < 2; m++) {
            int r = rowb + 16 * m + gid;
            float e00 = tanhf(acc[m][na][0] + bb0), e01 = tanhf(acc[m][na][1] + bb1);
            float e10 = tanhf(acc[m][na][2] + bb0), e11 = tanhf(acc[m][na][3] + bb1);
            unsigned hp, lp;
            packpairh(e00, e01, hp, lp);
            eH[r * 68 + pw] = hp; eL[r * 68 + pw] = lp;
            packpairh(e10, e11, hp, lp);
            eH[(r + 8) * 68 + pw] = hp; eL[(r + 8) * 68 + pw] = lp;
            p2[2 * m]     += e00 * e00 + e01 * e01;
            p2[2 * m + 1] += e10 * e10 + e11 * e11;
        }
    }
#pragma unroll
    for (int j = 0; j < 4; j++) {
        p2[j] += __shfl_xor_sync(0xffffffffu, p2[j], 1);
        p2[j] += __shfl_xor_sync(0xffffffffu, p2[j], 2);
    }
    if (q == 0) {
#pragma unroll
        for (int m = 0; m < 2; m++) {
            esqP[wn * 128 + rowb + 16 * m + gid]     = p2[2 * m];
            esqP[wn * 128 + rowb + 16 * m + gid + 8] = p2[2 * m + 1];
        }
    }
    __syncthreads();
    {
        const int mt = w >> 1, nt = w & 1;
        float d4[4] = {0.f, 0.f, 0.f, 0.f};
#pragma unroll
        for (int term = 0; term < 3; term++) {
            const unsigned* Aop = (term == 1) ? eL : eH;
            const unsigned* Bop = (term == 2) ? atL : atH;
#pragma unroll
            for (int ks = 0; ks < 8; ks++) {
                int b = (mt * 16 + gid) * 68 + ks * 8 + q;
                unsigned a[4] = {Aop[b], Aop[b + 544], Aop[b + 4], Aop[b + 548]};
                int bb = (nt * 8 + gid) * 68 + ks * 8 + q;
                unsigned bh[2] = {Bop[bb], Bop[bb + 4]};
                mma16h(d4, a, bh);
            }
        }
        int r = mt * 16 + gid, cc = nt * 8 + 2 * q;
        dotS[r * 20 + cc] = d4[0];       dotS[r * 20 + cc + 1] = d4[1];
        dotS[(r + 8) * 20 + cc] = d4[2]; dotS[(r + 8) * 20 + cc + 1] = d4[3];
    }
    __syncthreads();
    if (t < 128) {
        float esqv = esqP[t] + esqP[128 + t] + esqP[256 + t] + esqP[384 + t];
        float d[10];
#pragma unroll
        for (int k = 0; k < 10; k++)
            d[k] = sqrtf(fmaxf(esqv - 2.f * dotS[t * 20 + k] + asqS[k], 0.f));
        float dmin = d[0];
#pragma unroll
        for (int k = 1; k < 10; k++) dmin = fminf(dmin, d[k]);
        float s[10], Z = 0.f;
#pragma unroll
        for (int k = 0; k < 10; k++) { s[k] = expf(-2.f * (d[k] - dmin)); Z += s[k]; }
        float invZ = 1.f / Z;
#pragma unroll
        for (int k = 0; k < 10; k++) sS[t * 12 + k] = s[k] * invZ;
    }

    float acc2[2][4];
#pragma unroll
    for (int nf = 0; nf < 2; nf++)
#pragma unroll
        for (int j = 0; j < 4; j++) acc2[nf][j] = 0.f;

    for (int g = 0; g < 5; g++) {
        __syncthreads();
        for (int i = t; i < 2048; i += 512) {
            int j = i >> 4, c4 = i & 15;
            cpa16(wbuf + j * 68 + c4 * 4, g_we1p + g * 8192 + j * 64 + c4 * 4);
        }
        CPCOMMIT;
        if (t < 128) sBe[t] = be1[g * 128 + t];
        for (int i = t; i < 272; i += 512)
            ((uint4*)B2)[i] = ((const uint4*)(g_w2c + g * 1088))[i];
        CPWAIT0;
        __syncthreads();

        float acce[2][4][4];
#pragma unroll
        for (int m = 0; m < 2; m++)
#pragma unroll
            for (int na = 0; na < 4; na++)
#pragma unroll
                for (int j = 0; j < 4; j++) acce[m][na][j] = 0.f;
#pragma unroll
        for (int ks = 0; ks < 8; ks++) {
            unsigned a[2][4];
#pragma unroll
            for (int m = 0; m < 2; m++) {
                int b = (rowb + 16 * m + gid) * 68 + ks * 8 + q;
                a[m][0] = eH[b]; a[m][1] = eH[b + 544]; a[m][2] = eH[b + 4]; a[m][3] = eH[b + 548];
            }
#pragma unroll
            for (int na = 0; na < 4; na++) {
                int bb = (colb + 8 * na + gid) * 68 + ks * 8 + q;
                unsigned bh[2] = {wbuf[bb], wbuf[bb + 4]};
                mma16h(acce[0][na], a[0], bh);
                mma16h(acce[1][na], a[1], bh);
            }
        }
        __syncthreads();
#pragma unroll
        for (int na = 0; na < 4; na++) {
            int jc = colb + 8 * na + 2 * q, pw = wn * 16 + 4 * na + q;
            float bia0 = sBe[jc], bia1 = sBe[jc + 1];
            int k0 = 2 * g + (jc >> 6);
#pragma unroll
            for (int m = 0; m < 2; m++) {
                int rr = rowb + 16 * m + gid;
                float s0 = sS[rr * 12 + k0], s1 = sS[(rr + 8) * 12 + k0];
                wbuf[rr * 68 + pw] = packh(fmaxf(acce[m][na][0] + bia0, 0.f) * s0,
                                           fmaxf(acce[m][na][1] + bia1, 0.f) * s0);
                wbuf[(rr + 8) * 68 + pw] = packh(fmaxf(acce[m][na][2] + bia0, 0.f) * s1,
                                                 fmaxf(acce[m][na][3] + bia1, 0.f) * s1);
            }
        }
        __syncthreads();
        if (w < 8) {
#pragma unroll
            for (int ks = 0; ks < 8; ks++) {
                int b = (w * 16 + gid) * 68 + ks * 8 + q;
                unsigned a2[4] = {wbuf[b], wbuf[b + 544], wbuf[b + 4], wbuf[b + 548]};
#pragma unroll
                for (int nf = 0; nf < 2; nf++) {
                    int bb = (nf * 8 + gid) * 68 + ks * 8 + q;
                    unsigned bh[2] = {B2[bb], B2[bb + 4]};
                    mma16h(acc2[nf], a2, bh);
                }
            }
        }
    }
    if (w < 8) {
        const int rl = w * 16 + gid;
        const size_t r = row0 + rl;
        float b0 = 0.f, b1 = 0.f, b2a = 0.f, b3 = 0.f;
        float c0 = 0.f, c1 = 0.f, c2 = 0.f, c3 = 0.f;
#pragma unroll
        for (int k = 0; k < 10; k++) {
            float s0 = sS[rl * 12 + k], s1 = sS[(rl + 8) * 12 + k];
            float w0 = be2S[k * 10 + 2 * q], w1 = be2S[k * 10 + 2 * q + 1];
            b0 += s0 * w0; b1 += s0 * w1; b2a += s1 * w0; b3 += s1 * w1;
            if (q == 0) {
                float w8 = be2S[k * 10 + 8], w9 = be2S[k * 10 + 9];
                c0 += s0 * w8; c1 += s0 * w9; c2 += s1 * w8; c3 += s1 * w9;
            }
        }
        out[r * 10 + 2 * q]           = acc2[0][0] + b0;
        out[r * 10 + 2 * q + 1]       = acc2[0][1] + b1;
        out[(r + 8) * 10 + 2 * q]     = acc2[0][2] + b2a;
        out[(r + 8) * 10 + 2 * q + 1] = acc2[0][3] + b3;
        if (q == 0) {
            out[r * 10 + 8] = acc2[1][0] + c0;       out[r * 10 + 9] = acc2[1][1] + c1;
            out[(r + 8) * 10 + 8] = acc2[1][2] + c2; out[(r + 8) * 10 + 9] = acc2[1][3] + c3;
        }
    }
}

// ---------------------------------------------------------------------------
extern "C" void kernel_launch(void* const* d_in, const int* in_sizes, int n_in,
                              void* d_out, int out_size) {
    const float* state = (const float*)d_in[0];
    const float* W1    = (const float*)d_in[1];
    const float* b1    = (const float*)d_in[2];
    const float* gamma = (const float*)d_in[3];
    const float* beta  = (const float*)d_in[4];
    const float* W2    = (const float*)d_in[5];
    const float* b2    = (const float*)d_in[6];
    const float* We1   = (const float*)d_in[7];
    const float* be1   = (const float*)d_in[8];
    const float* We2   = (const float*)d_in[9];
    const float* be2   = (const float*)d_in[10];
    const float* att   = (const float*)d_in[11];
    float* out = (float*)d_out;

    const int SM1 = 13824 * 4, SMT = 25664 * 4;
    cudaFuncSetAttribute(k_gemm1, cudaFuncAttributeMaxDynamicSharedMemorySize, SM1);
    cudaFuncSetAttribute(k_tail,  cudaFuncAttributeMaxDynamicSharedMemorySize, SMT);

    k_prep <<<256, 256>>>(W1, We1, We2);
    k_gemm1<<<NBT, 512, SM1>>>(state, b1);
    k_stats<<<256, 256>>>(gamma, beta);
    k_fold <<<128, 256>>>(W2, b2);
    k_tail <<<NBT, 512, SMT>>>(att, be1, be2, out);
}

// round 16
// speedup vs baseline: 1.0009x; 1.0009x over previous
#include <cuda_runtime.h>
#include <cuda_fp16.h>
#include <math.h>

#define BTOT 262144
#define NBT  2048   // 128-row blocks (gemm1 + tail)

__device__ unsigned g_hh[(size_t)BTOT * 128];   // h fp16 pairs
__device__ float    g_psum[256 * NBT];
__device__ float    g_psq [256 * NBT];
__device__ float    g_A[256], g_Bb[256], g_b2p[128];
__device__ unsigned g_w1p[256 * 64];            // W1 fp16 pairs [n][pw]
__device__ unsigned short g_w2f[128 * 256];     // W2' fp16 [n][k]
__device__ unsigned g_we1p[5 * 128 * 64];       // We1 fp16 pairs
__device__ unsigned g_w2c [5 * 16 * 68];        // We2 fp16 pairs [g][a][j-pw]

__device__ __forceinline__ void mma16h(float* c, const unsigned* a, const unsigned* b) {
    asm volatile("mma.sync.aligned.m16n8k16.row.col.f32.f16.f16.f32 "
        "{%0,%1,%2,%3},{%4,%5,%6,%7},{%8,%9},{%0,%1,%2,%3};"
        : "+f"(c[0]), "+f"(c[1]), "+f"(c[2]), "+f"(c[3])
        : "r"(a[0]), "r"(a[1]), "r"(a[2]), "r"(a[3]), "r"(b[0]), "r"(b[1]));
}
__device__ __forceinline__ unsigned packh(float a, float b) {
    __half2 h = __floats2half2_rn(a, b); return *(unsigned*)&h;
}
__device__ __forceinline__ void packpairh(float v0, float v1, unsigned& hp, unsigned& lp) {
    __half h0 = __float2half_rn(v0), h1 = __float2half_rn(v1);
    hp = (unsigned)*(unsigned short*)&h0 | ((unsigned)*(unsigned short*)&h1 << 16);
    lp = packh(v0 - __half2float(h0), v1 - __half2float(h1));
}
__device__ __forceinline__ void cpa16(void* dst, const void* src) {
    unsigned d = (unsigned)__cvta_generic_to_shared(dst);
    asm volatile("cp.async.cg.shared.global [%0],[%1],16;\n" :: "r"(d), "l"(src));
}
#define CPCOMMIT asm volatile("cp.async.commit_group;\n")
#define CPWAIT0  asm volatile("cp.async.wait_group 0;\n")
#define CPWAIT1  asm volatile("cp.async.wait_group 1;\n")

// ------------------- prep -------------------
__global__ void k_prep(const float* __restrict__ W1, const float* __restrict__ We1,
                       const float* __restrict__ We2) {
    int idx = blockIdx.x * blockDim.x + threadIdx.x, st = gridDim.x * blockDim.x;
    for (int i = idx; i < 256 * 64; i += st) {
        int n = i >> 6, pw = i & 63;
        int k0 = 2 * pw, k1 = 2 * pw + 1;
        float v0 = (k0 < 100) ? W1[k0 * 256 + n] : 0.f;
        float v1 = (k1 < 100) ? W1[k1 * 256 + n] : 0.f;
        g_w1p[i] = packh(v0, v1);
    }
    for (int i = idx; i < 5 * 128 * 64; i += st) {
        int g = i >> 13, r = i & 8191, j = r >> 6, ep = r & 63;
        int sub = j >> 6, jl = j & 63;
        float v0 = We1[((size_t)(2 * g + sub) * 128 + 2 * ep) * 64 + jl];
        float v1 = We1[((size_t)(2 * g + sub) * 128 + 2 * ep + 1) * 64 + jl];
        g_we1p[i] = packh(v0, v1);
    }
    for (int i = idx; i < 5 * 16 * 68; i += st) {
        int g = i / 1088, r = i - g * 1088, a = r / 68, pw = r - a * 68;
        float v0 = 0.f, v1 = 0.f;
        if (a < 10 && pw < 64) {
            int j0 = 2 * pw, j1 = 2 * pw + 1;
            v0 = We2[(size_t)((2 * g + (j0 >> 6)) * 64 + (j0 & 63)) * 10 + a];
            v1 = We2[(size_t)((2 * g + (j1 >> 6)) * 64 + (j1 & 63)) * 10 + a];
        }
        g_w2c[i] = packh(v0, v1);
    }
}

// -- K1: h = relu(state@W1+b1). 128x256 tile, 512 thr, single fp16, K=112. --
__global__ __launch_bounds__(512, 2)
void k_gemm1(const float* __restrict__ state, const float* __restrict__ b1) {
    extern __shared__ unsigned sm[];
    unsigned* As = sm;             // [128][36]
    unsigned* Bs = sm + 4608;      // [256][36]; end 13824 words
    const int t = threadIdx.x, w = t >> 5, lane = t & 31;
    const int gid = lane >> 2, q = lane & 3;
    const int wm = w >> 2, wn = w & 3, rowb = wm * 32, colb = wn * 64;
    const size_t row0 = (size_t)blockIdx.x * 128;

    float acc[2][8][4];
#pragma unroll
    for (int m = 0; m < 2; m++)
#pragma unroll
        for (int na = 0; na < 8; na++)
#pragma unroll
            for (int j = 0; j < 4; j++) acc[m][na][j] = 0.f;

    for (int kc = 0; kc < 2; kc++) {
        __syncthreads();
        {
            int r = t >> 2, sl = t & 3, c0 = kc * 64 + sl * 16;
            float vv[16];
#pragma unroll
            for (int u = 0; u < 4; u++) {
                int k = c0 + u * 4;
                float4 x = (k < 100) ? *(const float4*)(state + (row0 + r) * 100 + k)
                                     : make_float4(0.f, 0.f, 0.f, 0.f);
                vv[4 * u] = x.x; vv[4 * u + 1] = x.y; vv[4 * u + 2] = x.z; vv[4 * u + 3] = x.w;
            }
            unsigned H[8];
#pragma unroll
            for (int u = 0; u < 8; u++) H[u] = packh(vv[2 * u], vv[2 * u + 1]);
            *(uint4*)(As + r * 36 + sl * 8)     = make_uint4(H[0], H[1], H[2], H[3]);
            *(uint4*)(As + r * 36 + sl * 8 + 4) = make_uint4(H[4], H[5], H[6], H[7]);
        }
        for (int i = t; i < 2048; i += 512) {
            int n = i >> 3, c8 = i & 7;
            *(uint4*)(Bs + n * 36 + c8 * 4) =
                *(const uint4*)(g_w1p + (size_t)n * 64 + kc * 32 + c8 * 4);
        }
        __syncthreads();
        const int kcnt = kc ? 3 : 4;
        for (int ks = 0; ks < kcnt; ks++) {
            unsigned ah[2][4];
#pragma unroll
            for (int m = 0; m < 2; m++) {
                int b = (rowb + 16 * m + gid) * 36 + ks * 8 + q;
                ah[m][0] = As[b]; ah[m][1] = As[b + 288]; ah[m][2] = As[b + 4]; ah[m][3] = As[b + 292];
            }
#pragma unroll
            for (int na = 0; na < 8; na++) {
                int bb = (colb + 8 * na + gid) * 36 + ks * 8 + q;
                unsigned bh[2] = {Bs[bb], Bs[bb + 4]};
#pragma unroll
                for (int m = 0; m < 2; m++) mma16h(acc[m][na], ah[m], bh);
            }
        }
    }
    __syncthreads();
    float* sums = (float*)sm;      // [4][256]
    float* sqs  = sums + 1024;
#pragma unroll
    for (int na = 0; na < 8; na++) {
        int cg = colb + 8 * na + 2 * q;
        float bias0 = b1[cg], bias1 = b1[cg + 1];
        float p0 = 0.f, p1 = 0.f, q0 = 0.f, q1 = 0.f;
#pragma unroll
        for (int m = 0; m < 2; m++) {
            size_t r = row0 + rowb + 16 * m + gid;
            float v00 = fmaxf(acc[m][na][0] + bias0, 0.f), v01 = fmaxf(acc[m][na][1] + bias1, 0.f);
            float v10 = fmaxf(acc[m][na][2] + bias0, 0.f), v11 = fmaxf(acc[m][na][3] + bias1, 0.f);
            g_hh[r * 128 + (cg >> 1)]       = packh(v00, v01);
            g_hh[(r + 8) * 128 + (cg >> 1)] = packh(v10, v11);
            p0 += v00 + v10; p1 += v01 + v11;
            q0 += v00 * v00 + v10 * v10; q1 += v01 * v01 + v11 * v11;
        }
#pragma unroll
        for (int off = 4; off <= 16; off <<= 1) {
            p0 += __shfl_xor_sync(0xffffffffu, p0, off);
            p1 += __shfl_xor_sync(0xffffffffu, p1, off);
            q0 += __shfl_xor_sync(0xffffffffu, q0, off);
            q1 += __shfl_xor_sync(0xffffffffu, q1, off);
        }
        if (gid == 0) {
            sums[wm * 256 + cg] = p0; sums[wm * 256 + cg + 1] = p1;
            sqs [wm * 256 + cg] = q0; sqs [wm * 256 + cg + 1] = q1;
        }
    }
    __syncthreads();
    if (t < 256) {
        g_psum[t * NBT + blockIdx.x] = sums[t] + sums[256 + t] + sums[512 + t] + sums[768 + t];
        g_psq [t * NBT + blockIdx.x] = sqs[t] + sqs[256 + t] + sqs[512 + t] + sqs[768 + t];
    }
}

// ------------------- K2: BN stats finalize -------------------
__global__ __launch_bounds__(256)
void k_stats(const float* __restrict__ gamma, const float* __restrict__ beta) {
    const int c = blockIdx.x, t = threadIdx.x;
    float s = 0.f, qq = 0.f;
    for (int i = t; i < NBT; i += 256) { s += g_psum[c * NBT + i]; qq += g_psq[c * NBT + i]; }
#pragma unroll
    for (int off = 16; off; off >>= 1) {
        s += __shfl_xor_sync(0xffffffffu, s, off);
        qq += __shfl_xor_sync(0xffffffffu, qq, off);
    }
    __shared__ float ss[8], sq[8];
    if ((t & 31) == 0) { ss[t >> 5] = s; sq[t >> 5] = qq; }
    __syncthreads();
    if (t == 0) {
        float S = 0.f, Q = 0.f;
#pragma unroll
        for (int wv = 0; wv < 8; wv++) { S += ss[wv]; Q += sq[wv]; }
        const float inv_n = 1.f / (float)BTOT;
        float mu = S * inv_n;
        float var = Q * inv_n - mu * mu;
        float rstd = rsqrtf(var + 1e-5f);
        float gg = gamma[c];
        g_A[c] = rstd * gg;
        g_Bb[c] = beta[c] - mu * rstd * gg;
    }
}

// ------------- K2b: fold BN into W2 (fp16) + b2' ---------------
__global__ __launch_bounds__(256)
void k_fold(const float* __restrict__ W2, const float* __restrict__ b2) {
    const int n = blockIdx.x, k = threadIdx.x;
    float wv = W2[k * 128 + n];
    __half hf = __float2half_rn(g_A[k] * wv);
    g_w2f[n * 256 + k] = *(unsigned short*)&hf;
    float p = g_Bb[k] * wv;
#pragma unroll
    for (int off = 16; off; off >>= 1) p += __shfl_xor_sync(0xffffffffu, p, off);
    __shared__ float red[8];
    if ((k & 31) == 0) red[k >> 5] = p;
    __syncthreads();
    if (k == 0) {
        float S = 0.f;
#pragma unroll
        for (int i = 0; i < 8; i++) S += red[i];
        g_b2p[n] = b2[n] + S;
    }
}

// -- K3: fused tail (128 rows, 512 thr): enc GEMM + dist + softmax + experts
__global__ __launch_bounds__(512, 2)
void k_tail(const float* __restrict__ att, const float* __restrict__ be1,
            const float* __restrict__ be2, float* __restrict__ out) {
    extern __shared__ unsigned sm[];
    unsigned* Bs  = sm + 9216;           // phase A: A-dbuf 0/4608, Bs [128][36]
    unsigned* eH   = sm;                 // [128][68]
    unsigned* eL   = sm + 8704;          // [128][68] (dead after distance)
    unsigned* wbuf = sm + 8704;          // [128][68] We1 -> eh
    unsigned* atH = sm + 17408;          // [16][68]
    unsigned* atL = sm + 18496;
    float* b2ps = (float*)(sm + 19584);  // [128]
    float* asqS = (float*)(sm + 19712);  // [16]
    float* dotS = (float*)(sm + 19728);  // [128][20]
    float* esqP = (float*)(sm + 22288);  // [4][128]
    float* sS   = (float*)(sm + 22800);  // [128][12]
    float* sBe  = (float*)(sm + 24336);  // [128]
    float* be2S = (float*)(sm + 24464);  // [112]
    unsigned* B2 = sm + 24576;           // [16][68]; total 25664 words
    const int t = threadIdx.x, w = t >> 5, lane = t & 31;
    const int gid = lane >> 2, q = lane & 3;
    const int wm = w >> 2, wn = w & 3, rowb = wm * 32, colb = wn * 32;
    const size_t row0 = (size_t)blockIdx.x * 128;
    const unsigned* w2w = (const unsigned*)g_w2f;

    for (int i = t; i < 1088; i += 512) {
        int n = i / 68, pw = i - n * 68;
        float v0 = 0.f, v1 = 0.f;
        if (n < 10 && pw < 64) { v0 = att[n * 128 + 2 * pw]; v1 = att[n * 128 + 2 * pw + 1]; }
        unsigned hp, lp;
        packpairh(v0, v1, hp, lp);
        atH[i] = hp; atL[i] = lp;
    }
    if (t < 128) b2ps[t] = g_b2p[t];
    if (t >= 128 && t < 144) {
        int k = t - 128;
        float a2 = 0.f;
        if (k < 10)
            for (int c = 0; c < 128; c++) { float x = att[k * 128 + c]; a2 += x * x; }
        asqS[k] = a2;
    }
    if (t >= 144 && t < 244) be2S[t - 144] = be2[t - 144];

    float acc[2][4][4];
#pragma unroll
    for (int m = 0; m < 2; m++)
#pragma unroll
        for (int na = 0; na < 4; na++)
#pragma unroll
            for (int j = 0; j < 4; j++) acc[m][na][j] = 0.f;

    for (int i = t; i < 1024; i += 512) {
        int r = i >> 3, c8 = i & 7;
        cpa16(sm + r * 36 + c8 * 4, g_hh + (row0 + r) * 128 + c8 * 4);
    }
    CPCOMMIT;
    for (int kc = 0; kc < 4; kc++) {
        if (kc < 3) {
            unsigned* dst = sm + ((kc + 1) & 1) * 4608;
            for (int i = t; i < 1024; i += 512) {
                int r = i >> 3, c8 = i & 7;
                cpa16(dst + r * 36 + c8 * 4, g_hh + (row0 + r) * 128 + (kc + 1) * 32 + c8 * 4);
            }
            CPCOMMIT;
        }
        for (int i = t; i < 1024; i += 512) {
            int n = i >> 3, c8 = i & 7;
            *(uint4*)(Bs + n * 36 + c8 * 4) = *(const uint4*)(w2w + (size_t)n * 128 + kc * 32 + c8 * 4);
        }
        if (kc < 3) { CPWAIT1; } else { CPWAIT0; }
        __syncthreads();
        unsigned* As = sm + (kc & 1) * 4608;
#pragma unroll
        for (int ks = 0; ks < 4; ks++) {
            unsigned ah[2][4];
#pragma unroll
            for (int m = 0; m < 2; m++) {
                int b = (rowb + 16 * m + gid) * 36 + ks * 8 + q;
                ah[m][0] = As[b]; ah[m][1] = As[b + 288]; ah[m][2] = As[b + 4]; ah[m][3] = As[b + 292];
            }
#pragma unroll
            for (int na = 0; na < 4; na++) {
                int bb = (colb + 8 * na + gid) * 36 + ks * 8 + q;
                unsigned bh[2] = {Bs[bb], Bs[bb + 4]};
#pragma unroll
                for (int m = 0; m < 2; m++) mma16h(acc[m][na], ah[m], bh);
            }
        }
        __syncthreads();
    }
    float p2[4] = {0.f, 0.f, 0.f, 0.f};
#pragma unroll
    for (int na = 0; na < 4; na++) {
        int cl = colb + 8 * na + 2 * q, pw = (cl >> 1);
        float bb0 = b2ps[cl], bb1 = b2ps[cl + 1];
#pragma unroll
        for (int m = 0; m < 2; m++) {
            int r = rowb + 16 * m + gid;
            float e00 = tanhf(acc[m][na][0] + bb0), e01 = tanhf(acc[m][na][1] + bb1);
            float e10 = tanhf(acc[m][na][2] + bb0), e11 = tanhf(acc[m][na][3] + bb1);
            unsigned hp, lp;
            packpairh(e00, e01, hp, lp);
            eH[r * 68 + pw] = hp; eL[r * 68 + pw] = lp;
            packpairh(e10, e11, hp, lp);
            eH[(r + 8) * 68 + pw] = hp; eL[(r + 8) * 68 + pw] = lp;
            p2[2 * m]     += e00 * e00 + e01 * e01;
            p2[2 * m + 1] += e10 * e10 + e11 * e11;
        }
    }
#pragma unroll
    for (int j = 0; j < 4; j++) {
        p2[j] += __shfl_xor_sync(0xffffffffu, p2[j], 1);
        p2[j] += __shfl_xor_sync(0xffffffffu, p2[j], 2);
    }
    if (q == 0) {
#pragma unroll
        for (int m = 0; m < 2; m++) {
            esqP[wn * 128 + rowb + 16 * m + gid]     = p2[2 * m];
            esqP[wn * 128 + rowb + 16 * m + gid + 8] = p2[2 * m + 1];
        }
    }
    __syncthreads();
    {
        const int mt = w >> 1, nt = w & 1;
        float d4[4] = {0.f, 0.f, 0.f, 0.f};
#pragma unroll
        for (int term = 0; term < 3; term++) {
            const unsigned* Aop = (term == 1) ? eL : eH;
            const unsigned* Bop = (term == 2) ? atL : atH;
#pragma unroll
            for (int ks = 0; ks < 8; ks++) {
                int b = (mt * 16 + gid) * 68 + ks * 8 + q;
                unsigned a[4] = {Aop[b], Aop[b + 544], Aop[b + 4], Aop[b + 548]};
                int bb = (nt * 8 + gid) * 68 + ks * 8 + q;
                unsigned bh[2] = {Bop[bb], Bop[bb + 4]};
                mma16h(d4, a, bh);
            }
        }
        int r = mt * 16 + gid, cc = nt * 8 + 2 * q;
        dotS[r * 20 + cc] = d4[0];       dotS[r * 20 + cc + 1] = d4[1];
        dotS[(r + 8) * 20 + cc] = d4[2]; dotS[(r + 8) * 20 + cc + 1] = d4[3];
    }
    __syncthreads();
    if (t < 128) {
        float esqv = esqP[t] + esqP[128 + t] + esqP[256 + t] + esqP[384 + t];
        float d[10];
#pragma unroll
        for (int k = 0; k < 10; k++)
            d[k] = sqrtf(fmaxf(esqv - 2.f * dotS[t * 20 + k] + asqS[k], 0.f));
        float dmin = d[0];
#pragma unroll
        for (int k = 1; k < 10; k++) dmin = fminf(dmin, d[k]);
        float s[10], Z = 0.f;
#pragma unroll
        for (int k = 0; k < 10; k++) { s[k] = expf(-2.f * (d[k] - dmin)); Z += s[k]; }
        float invZ = 1.f / Z;
#pragma unroll
        for (int k = 0; k < 10; k++) sS[t * 12 + k] = s[k] * invZ;
    }

    float acc2[2][4];
#pragma unroll
    for (int nf = 0; nf < 2; nf++)
#pragma unroll
        for (int j = 0; j < 4; j++) acc2[nf][j] = 0.f;

    for (int g = 0; g < 5; g++) {
        __syncthreads();
        for (int i = t; i < 2048; i += 512) {
            int j = i >> 4, c4 = i & 15;
            cpa16(wbuf + j * 68 + c4 * 4, g_we1p + g * 8192 + j * 64 + c4 * 4);
        }
        CPCOMMIT;
        if (t < 128) sBe[t] = be1[g * 128 + t];
        for (int i = t; i < 272; i += 512)
            ((uint4*)B2)[i] = ((const uint4*)(g_w2c + g * 1088))[i];
        CPWAIT0;
        __syncthreads();

        float acce[2][4][4];
#pragma unroll
        for (int m = 0; m < 2; m++)
#pragma unroll
            for (int na = 0; na < 4; na++)
#pragma unroll
                for (int j = 0; j < 4; j++) acce[m][na][j] = 0.f;
#pragma unroll
        for (int ks = 0; ks < 8; ks++) {
            unsigned a[2][4];
#pragma unroll
            for (int m = 0; m < 2; m++) {
                int b = (rowb + 16 * m + gid) * 68 + ks * 8 + q;
                a[m][0] = eH[b]; a[m][1] = eH[b + 544]; a[m][2] = eH[b + 4]; a[m][3] = eH[b + 548];
            }
#pragma unroll
            for (int na = 0; na < 4; na++) {
                int bb = (colb + 8 * na + gid) * 68 + ks * 8 + q;
                unsigned bh[2] = {wbuf[bb], wbuf[bb + 4]};
                mma16h(acce[0][na], a[0], bh);
                mma16h(acce[1][na], a[1], bh);
            }
        }
        __syncthreads();
#pragma unroll
        for (int na = 0; na < 4; na++) {
            int jc = colb + 8 * na + 2 * q, pw = wn * 16 + 4 * na + q;
            float bia0 = sBe[jc], bia1 = sBe[jc + 1];
            int k0 = 2 * g + (jc >> 6);
#pragma unroll
            for (int m = 0; m < 2; m++) {
                int rr = rowb + 16 * m + gid;
                float s0 = sS[rr * 12 + k0], s1 = sS[(rr + 8) * 12 + k0];
                wbuf[rr * 68 + pw] = packh(fmaxf(acce[m][na][0] + bia0, 0.f) * s0,
                                           fmaxf(acce[m][na][1] + bia1, 0.f) * s0);
                wbuf[(rr + 8) * 68 + pw] = packh(fmaxf(acce[m][na][2] + bia0, 0.f) * s1,
                                                 fmaxf(acce[m][na][3] + bia1, 0.f) * s1);
            }
        }
        __syncthreads();
        if (w < 8) {
#pragma unroll
            for (int ks = 0; ks < 8; ks++) {
                int b = (w * 16 + gid) * 68 + ks * 8 + q;
                unsigned a2[4] = {wbuf[b], wbuf[b + 544], wbuf[b + 4], wbuf[b + 548]};
#pragma unroll
                for (int nf = 0; nf < 2; nf++) {
                    int bb = (nf * 8 + gid) * 68 + ks * 8 + q;
                    unsigned bh[2] = {B2[bb], B2[bb + 4]};
                    mma16h(acc2[nf], a2, bh);
                }
            }
        }
    }
    if (w < 8) {
        const int rl = w * 16 + gid;
        const size_t r = row0 + rl;
        float b0 = 0.f, b1 = 0.f, b2a = 0.f, b3 = 0.f;
        float c0 = 0.f, c1 = 0.f, c2 = 0.f, c3 = 0.f;
#pragma unroll
        for (int k = 0; k < 10; k++) {
            float s0 = sS[rl * 12 + k], s1 = sS[(rl + 8) * 12 + k];
            float w0 = be2S[k * 10 + 2 * q], w1 = be2S[k * 10 + 2 * q + 1];
            b0 += s0 * w0; b1 += s0 * w1; b2a += s1 * w0; b3 += s1 * w1;
            if (q == 0) {
                float w8 = be2S[k * 10 + 8], w9 = be2S[k * 10 + 9];
                c0 += s0 * w8; c1 += s0 * w9; c2 += s1 * w8; c3 += s1 * w9;
            }
        }
        out[r * 10 + 2 * q]           = acc2[0][0] + b0;
        out[r * 10 + 2 * q + 1]       = acc2[0][1] + b1;
        out[(r + 8) * 10 + 2 * q]     = acc2[0][2] + b2a;
        out[(r + 8) * 10 + 2 * q + 1] = acc2[0][3] + b3;
        if (q == 0) {
            out[r * 10 + 8] = acc2[1][0] + c0;       out[r * 10 + 9] = acc2[1][1] + c1;
            out[(r + 8) * 10 + 8] = acc2[1][2] + c2; out[(r + 8) * 10 + 9] = acc2[1][3] + c3;
        }
    }
}

// ---------------------------------------------------------------------------
extern "C" void kernel_launch(void* const* d_in, const int* in_sizes, int n_in,
                              void* d_out, int out_size) {
    const float* state = (const float*)d_in[0];
    const float* W1    = (const float*)d_in[1];
    const float* b1    = (const float*)d_in[2];
    const float* gamma = (const float*)d_in[3];
    const float* beta  = (const float*)d_in[4];
    const float* W2    = (const float*)d_in[5];
    const float* b2    = (const float*)d_in[6];
    const float* We1   = (const float*)d_in[7];
    const float* be1   = (const float*)d_in[8];
    const float* We2   = (const float*)d_in[9];
    const float* be2   = (const float*)d_in[10];
    const float* att   = (const float*)d_in[11];
    float* out = (float*)d_out;

    const int SM1 = 13824 * 4, SMT = 25664 * 4;
    cudaFuncSetAttribute(k_gemm1, cudaFuncAttributeMaxDynamicSharedMemorySize, SM1);
    cudaFuncSetAttribute(k_tail,  cudaFuncAttributeMaxDynamicSharedMemorySize, SMT);

    k_prep <<<256, 256>>>(W1, We1, We2);
    k_gemm1<<<NBT, 512, SM1>>>(state, b1);
    k_stats<<<256, 256>>>(gamma, beta);
    k_fold <<<128, 256>>>(W2, b2);
    k_tail <<<NBT, 512, SMT>>>(att, be1, be2, out);
}